// round 1
// baseline (speedup 1.0000x reference)
#include <cuda_runtime.h>

#define SEQ 4096
#define DM  768
#define NH  12
#define HD  64

// ---------------- scratch (no allocations allowed) ----------------
__device__ float g_Q[SEQ * DM];
__device__ float g_K[SEQ * DM];
__device__ float g_V[SEQ * DM];
__device__ float g_att[SEQ * DM];

__device__ __forceinline__ float fexp2(float x) {
    float y;
    asm("ex2.approx.ftz.f32 %0, %1;" : "=f"(y) : "f"(x));
    return y;
}

#define OUTER4x4(ACC, A4, B4)                                                               \
    ACC[0][0] += A4.x * B4.x; ACC[0][1] += A4.x * B4.y; ACC[0][2] += A4.x * B4.z; ACC[0][3] += A4.x * B4.w; \
    ACC[1][0] += A4.y * B4.x; ACC[1][1] += A4.y * B4.y; ACC[1][2] += A4.y * B4.z; ACC[1][3] += A4.y * B4.w; \
    ACC[2][0] += A4.z * B4.x; ACC[2][1] += A4.z * B4.y; ACC[2][2] += A4.z * B4.z; ACC[2][3] += A4.z * B4.w; \
    ACC[3][0] += A4.w * B4.x; ACC[3][1] += A4.w * B4.y; ACC[3][2] += A4.w * B4.z; ACC[3][3] += A4.w * B4.w;

// ---------------- GEMM: C[M,N] = A[M,K] * B[N,K]^T  (both row-major, K contiguous) ----------------
#define GBM 64
#define GBN 64
#define GBK 16
#define GPAD 4
#define GST (GBM + GPAD)   // 68 floats per smem row (16B-aligned stride)

__global__ __launch_bounds__(256)
void gemm_nt(const float* __restrict__ A,
             const float* __restrict__ B0, const float* __restrict__ B1, const float* __restrict__ B2,
             float* __restrict__ C0, float* __restrict__ C1, float* __restrict__ C2,
             int M, int N, int K)
{
    const float* B = (blockIdx.z == 0) ? B0 : ((blockIdx.z == 1) ? B1 : B2);
    float*       C = (blockIdx.z == 0) ? C0 : ((blockIdx.z == 1) ? C1 : C2);

    __shared__ float Ats[GBK][GST];   // transposed: [k][m]
    __shared__ float Bts[GBK][GST];   // transposed: [k][n]

    const int tid = threadIdx.x;
    const int ty  = tid >> 4;         // 0..15  (row group)
    const int tx  = tid & 15;         // 0..15  (col group)
    const int m0  = blockIdx.y * GBM;
    const int n0  = blockIdx.x * GBN;

    // loader mapping: one float4 per thread per tile per matrix
    const int lr = tid >> 2;          // 0..63 : tile row
    const int lk = (tid & 3) * 4;     // 0,4,8,12 : k offset of the float4

    const float* Ap = A + (size_t)(m0 + lr) * K + lk;
    const float* Bp = B + (size_t)(n0 + lr) * K + lk;

    float4 a_reg = *(const float4*)Ap;
    float4 b_reg = *(const float4*)Bp;

    float acc[4][4] = {};
    const int T = K / GBK;

    for (int t = 0; t < T; t++) {
        // scatter-transpose current tile into smem
        Ats[lk + 0][lr] = a_reg.x; Ats[lk + 1][lr] = a_reg.y;
        Ats[lk + 2][lr] = a_reg.z; Ats[lk + 3][lr] = a_reg.w;
        Bts[lk + 0][lr] = b_reg.x; Bts[lk + 1][lr] = b_reg.y;
        Bts[lk + 2][lr] = b_reg.z; Bts[lk + 3][lr] = b_reg.w;
        __syncthreads();

        if (t + 1 < T) {
            a_reg = *(const float4*)(Ap + (t + 1) * GBK);
            b_reg = *(const float4*)(Bp + (t + 1) * GBK);
        }

#pragma unroll
        for (int kk = 0; kk < GBK; kk++) {
            float4 a4 = *(const float4*)&Ats[kk][ty * 4];
            float4 b4 = *(const float4*)&Bts[kk][tx * 4];
            OUTER4x4(acc, a4, b4);
        }
        __syncthreads();
    }

#pragma unroll
    for (int ii = 0; ii < 4; ii++) {
        float4 o = make_float4(acc[ii][0], acc[ii][1], acc[ii][2], acc[ii][3]);
        *(float4*)&C[(size_t)(m0 + ty * 4 + ii) * N + n0 + tx * 4] = o;
    }
}

// ---------------- Flash attention, fp32, causal, online softmax (base-2) ----------------
#define FPAD 4
#define FST (HD + FPAD)   // 68

__global__ __launch_bounds__(256)
void flash_attn(const float* __restrict__ Qg, const float* __restrict__ Kg,
                const float* __restrict__ Vg, float* __restrict__ O)
{
    extern __shared__ float sm[];
    float* Qts = sm;                  // [HD][FST]  Q transposed: Qts[d*FST + m]
    float* KP  = sm + HD * FST;       // [64][FST]  K transposed [d][n], reused as P transposed [n][m]
    float* Vs  = sm + 2 * HD * FST;   // [64][FST]  V row-major [n][d]

    const int qt  = blockIdx.x;       // query tile (64 rows)
    const int h   = blockIdx.y;       // head
    const int tid = threadIdx.x;
    const int ty  = tid >> 4;         // row group 0..15
    const int tx  = tid & 15;         // col group 0..15

    // load Q tile transposed (1024 float4 over 256 threads)
    for (int i = tid; i < 1024; i += 256) {
        int rr = i >> 4, c4 = i & 15;
        float4 v = *(const float4*)&Qg[(size_t)(qt * 64 + rr) * DM + h * HD + c4 * 4];
        int d = c4 * 4;
        Qts[(d + 0) * FST + rr] = v.x;
        Qts[(d + 1) * FST + rr] = v.y;
        Qts[(d + 2) * FST + rr] = v.z;
        Qts[(d + 3) * FST + rr] = v.w;
    }

    float acc[4][4] = {};
    float m_i[4], l_i[4];
#pragma unroll
    for (int ii = 0; ii < 4; ii++) { m_i[ii] = -1e30f; l_i[ii] = 0.0f; }

    // softmax in base-2 domain: exp(s/8) == 2^(s * (log2e/8))
    const float scale2 = 0.125f * 1.4426950408889634f;

    for (int j = 0; j <= qt; j++) {
        // load K (transposed) and V (row-major) tiles
        for (int i = tid; i < 1024; i += 256) {
            int rr = i >> 4, c4 = i & 15;
            size_t gbase = (size_t)(j * 64 + rr) * DM + h * HD + c4 * 4;
            float4 kv = *(const float4*)&Kg[gbase];
            int d = c4 * 4;
            KP[(d + 0) * FST + rr] = kv.x;
            KP[(d + 1) * FST + rr] = kv.y;
            KP[(d + 2) * FST + rr] = kv.z;
            KP[(d + 3) * FST + rr] = kv.w;
            float4 vv = *(const float4*)&Vg[gbase];
            *(float4*)&Vs[rr * FST + c4 * 4] = vv;
        }
        __syncthreads();

        // S = Q K^T  (outer product over d)
        float s[4][4] = {};
#pragma unroll 8
        for (int d = 0; d < HD; d++) {
            float4 a4 = *(const float4*)&Qts[d * FST + ty * 4];
            float4 b4 = *(const float4*)&KP[d * FST + tx * 4];
            OUTER4x4(s, a4, b4);
        }

        // scale (+ causal mask on diagonal tile)
        if (j == qt) {
#pragma unroll
            for (int ii = 0; ii < 4; ii++)
#pragma unroll
                for (int jj = 0; jj < 4; jj++) {
                    int rg = ty * 4 + ii, cg = tx * 4 + jj;
                    s[ii][jj] = (cg <= rg) ? s[ii][jj] * scale2 : -1e30f;
                }
        } else {
#pragma unroll
            for (int ii = 0; ii < 4; ii++)
#pragma unroll
                for (int jj = 0; jj < 4; jj++)
                    s[ii][jj] *= scale2;
        }

        // online softmax: 16-lane (tx) reductions via shfl.xor
#pragma unroll
        for (int ii = 0; ii < 4; ii++) {
            float mx = fmaxf(fmaxf(s[ii][0], s[ii][1]), fmaxf(s[ii][2], s[ii][3]));
#pragma unroll
            for (int off = 1; off < 16; off <<= 1)
                mx = fmaxf(mx, __shfl_xor_sync(0xffffffffu, mx, off));
            float mnew = fmaxf(m_i[ii], mx);
            float alpha = fexp2(m_i[ii] - mnew);
            float sum = 0.0f;
#pragma unroll
            for (int jj = 0; jj < 4; jj++) {
                s[ii][jj] = fexp2(s[ii][jj] - mnew);
                sum += s[ii][jj];
            }
#pragma unroll
            for (int off = 1; off < 16; off <<= 1)
                sum += __shfl_xor_sync(0xffffffffu, sum, off);
            l_i[ii] = l_i[ii] * alpha + sum;
            m_i[ii] = mnew;
#pragma unroll
            for (int jj = 0; jj < 4; jj++)
                acc[ii][jj] *= alpha;
        }

        __syncthreads();   // everyone done reading KP as K

        // write P transposed into the K buffer: KP[n][m]
#pragma unroll
        for (int ii = 0; ii < 4; ii++)
#pragma unroll
            for (int jj = 0; jj < 4; jj++)
                KP[(tx * 4 + jj) * FST + ty * 4 + ii] = s[ii][jj];
        __syncthreads();

        // acc += P V  (outer product over n)
#pragma unroll 8
        for (int n = 0; n < 64; n++) {
            float4 a4 = *(const float4*)&KP[n * FST + ty * 4];
            float4 b4 = *(const float4*)&Vs[n * FST + tx * 4];
            OUTER4x4(acc, a4, b4);
        }
        __syncthreads();   // done with Vs/KP before next tile load
    }

    // normalize + store
#pragma unroll
    for (int ii = 0; ii < 4; ii++) {
        float inv = 1.0f / l_i[ii];
        float4 o = make_float4(acc[ii][0] * inv, acc[ii][1] * inv,
                               acc[ii][2] * inv, acc[ii][3] * inv);
        *(float4*)&O[(size_t)(qt * 64 + ty * 4 + ii) * DM + h * HD + tx * 4] = o;
    }
}

// ---------------- launch ----------------
extern "C" void kernel_launch(void* const* d_in, const int* in_sizes, int n_in,
                              void* d_out, int out_size)
{
    (void)in_sizes; (void)n_in; (void)out_size;
    const float* x  = (const float*)d_in[0];
    const float* Wq = (const float*)d_in[1];
    const float* Wk = (const float*)d_in[2];
    const float* Wv = (const float*)d_in[3];
    const float* Wp = (const float*)d_in[4];
    float* out = (float*)d_out;

    float *Q, *K, *V, *att;
    cudaGetSymbolAddress((void**)&Q,   g_Q);
    cudaGetSymbolAddress((void**)&K,   g_K);
    cudaGetSymbolAddress((void**)&V,   g_V);
    cudaGetSymbolAddress((void**)&att, g_att);

    const int flash_smem = 3 * HD * FST * (int)sizeof(float);  // 52224 B
    cudaFuncSetAttribute(flash_attn, cudaFuncAttributeMaxDynamicSharedMemorySize, flash_smem);

    // fused QKV projection: z selects weight/output
    dim3 gq(DM / GBN, SEQ / GBM, 3);
    gemm_nt<<<gq, 256>>>(x, Wq, Wk, Wv, Q, K, V, SEQ, DM, DM);

    // causal flash attention
    dim3 gf(SEQ / 64, NH);
    flash_attn<<<gf, 256, flash_smem>>>(Q, K, V, att);

    // output projection
    dim3 gp(DM / GBN, SEQ / GBM, 1);
    gemm_nt<<<gp, 256>>>(att, Wp, Wp, Wp, out, out, out, SEQ, DM, DM);
}

// round 3
// speedup vs baseline: 1.9399x; 1.9399x over previous
#include <cuda_runtime.h>
#include <cstdint>

#define SEQ 4096
#define DM  768
#define NH  12
#define HD  64

// ---------------- scratch (no allocations allowed) ----------------
__device__ float g_Q[SEQ * DM];
__device__ float g_K[SEQ * DM];
__device__ float g_V[SEQ * DM];
__device__ float g_att[SEQ * DM];

// ---------------- helpers ----------------
__device__ __forceinline__ uint32_t f2tf32(float x) {
    uint32_t y;
    asm("cvt.rna.tf32.f32 %0, %1;" : "=r"(y) : "f"(x));
    return y;
}
__device__ __forceinline__ float fexp2(float x) {
    float y;
    asm("ex2.approx.ftz.f32 %0, %1;" : "=f"(y) : "f"(x));
    return y;
}
// D += A*B  (m16n8k8 tf32, fp32 accumulate)
__device__ __forceinline__ void mma8(float* d,
                                     uint32_t a0, uint32_t a1, uint32_t a2, uint32_t a3,
                                     uint32_t b0, uint32_t b1) {
    asm volatile(
        "mma.sync.aligned.m16n8k8.row.col.f32.tf32.tf32.f32 "
        "{%0,%1,%2,%3}, {%4,%5,%6,%7}, {%8,%9}, {%0,%1,%2,%3};"
        : "+f"(d[0]), "+f"(d[1]), "+f"(d[2]), "+f"(d[3])
        : "r"(a0), "r"(a1), "r"(a2), "r"(a3), "r"(b0), "r"(b1));
}

// ================= GEMM: C[M,N] = A[M,K] * B[N,K]^T  (tf32 mma.sync) =================
// block tile 128x128x32, 8 warps, warp tile 64x32
#define GS 36   // smem row stride in words; 36 % 32 == 4 -> frag LDS conflict-free

__global__ __launch_bounds__(256, 2)
void gemm_tc(const float* __restrict__ A,
             const float* __restrict__ B0, const float* __restrict__ B1, const float* __restrict__ B2,
             float* __restrict__ C0, float* __restrict__ C1, float* __restrict__ C2,
             int M, int N, int K)
{
    const float* B = (blockIdx.z == 0) ? B0 : ((blockIdx.z == 1) ? B1 : B2);
    float*       C = (blockIdx.z == 0) ? C0 : ((blockIdx.z == 1) ? C1 : C2);

    __shared__ uint32_t As[128 * GS];
    __shared__ uint32_t Bs[128 * GS];

    const int tid  = threadIdx.x;
    const int wid  = tid >> 5;
    const int lane = tid & 31;
    const int g    = lane >> 2;    // group (row within fragment)
    const int tg   = lane & 3;     // thread-in-group
    const int wm   = (wid >> 2) * 64;  // warp m offset
    const int wn   = (wid & 3) * 32;   // warp n offset
    const int m0   = blockIdx.y * 128;
    const int n0   = blockIdx.x * 128;

    // loader: 2 threads per row, 16 floats each
    const int lrow = tid >> 1;
    const int lc   = (tid & 1) * 16;
    const float* Ap = A + (size_t)(m0 + lrow) * K + lc;
    const float* Bp = B + (size_t)(n0 + lrow) * K + lc;

    float4 pa[4], pb[4];
#pragma unroll
    for (int i = 0; i < 4; i++) {
        pa[i] = *(const float4*)(Ap + i * 4);
        pb[i] = *(const float4*)(Bp + i * 4);
    }

    float acc[4][4][4] = {};
    const int T = K / 32;   // 24

    for (int t = 0; t < T; t++) {
#pragma unroll
        for (int i = 0; i < 4; i++) {
            uint4 ua = make_uint4(f2tf32(pa[i].x), f2tf32(pa[i].y), f2tf32(pa[i].z), f2tf32(pa[i].w));
            *(uint4*)&As[lrow * GS + lc + i * 4] = ua;
            uint4 ub = make_uint4(f2tf32(pb[i].x), f2tf32(pb[i].y), f2tf32(pb[i].z), f2tf32(pb[i].w));
            *(uint4*)&Bs[lrow * GS + lc + i * 4] = ub;
        }
        __syncthreads();

        if (t + 1 < T) {
#pragma unroll
            for (int i = 0; i < 4; i++) {
                pa[i] = *(const float4*)(Ap + (t + 1) * 32 + i * 4);
                pb[i] = *(const float4*)(Bp + (t + 1) * 32 + i * 4);
            }
        }

#pragma unroll
        for (int ks = 0; ks < 4; ks++) {
            const int k0 = ks * 8;
            uint32_t af[4][4];
#pragma unroll
            for (int mt = 0; mt < 4; mt++) {
                const int r = wm + mt * 16 + g;
                af[mt][0] = As[r * GS + k0 + tg];
                af[mt][1] = As[(r + 8) * GS + k0 + tg];
                af[mt][2] = As[r * GS + k0 + tg + 4];
                af[mt][3] = As[(r + 8) * GS + k0 + tg + 4];
            }
#pragma unroll
            for (int nt = 0; nt < 4; nt++) {
                const int rn = wn + nt * 8 + g;
                uint32_t b0 = Bs[rn * GS + k0 + tg];
                uint32_t b1 = Bs[rn * GS + k0 + tg + 4];
#pragma unroll
                for (int mt = 0; mt < 4; mt++)
                    mma8(acc[mt][nt], af[mt][0], af[mt][1], af[mt][2], af[mt][3], b0, b1);
            }
        }
        __syncthreads();
    }

    // epilogue: C-fragment direct store (float2: cols 2tg, 2tg+1 contiguous)
#pragma unroll
    for (int mt = 0; mt < 4; mt++) {
        const int r0 = m0 + wm + mt * 16 + g;
#pragma unroll
        for (int nt = 0; nt < 4; nt++) {
            const int c = n0 + wn + nt * 8 + tg * 2;
            *(float2*)&C[(size_t)r0 * N + c]       = make_float2(acc[mt][nt][0], acc[mt][nt][1]);
            *(float2*)&C[(size_t)(r0 + 8) * N + c] = make_float2(acc[mt][nt][2], acc[mt][nt][3]);
        }
    }
}

// ================= Flash attention (tf32 mma.sync, causal, online softmax) =================
// block: 64 q-rows x 1 head, 4 warps (warp owns 16 rows); KV tile 64
#define QS_ST 68   // 68 % 32 == 4  (A/B frag pattern 4g+tg conflict-free)
#define VS_ST 72   // 72 % 32 == 8  (V b-frag pattern 8tg+g conflict-free)
#define SM_Q  0
#define SM_KP (64 * QS_ST)
#define SM_V  (2 * 64 * QS_ST)
#define FLASH_SMEM_WORDS (2 * 64 * QS_ST + 64 * VS_ST)

__global__ __launch_bounds__(128)
void flash_tc(const float* __restrict__ Qg, const float* __restrict__ Kg,
              const float* __restrict__ Vg, float* __restrict__ O)
{
    extern __shared__ uint32_t sm[];
    uint32_t* Qs = sm + SM_Q;
    uint32_t* KP = sm + SM_KP;   // K tile, then reused as P tile
    uint32_t* Vs = sm + SM_V;

    const int qt   = blockIdx.x;
    const int h    = blockIdx.y;
    const int tid  = threadIdx.x;
    const int lane = tid & 31;
    const int g    = lane >> 2;
    const int tg   = lane & 3;
    const int wm   = (tid >> 5) * 16;   // warp row offset in tile

    // loader: 2 threads per row, 32 floats each
    const int lrow = tid >> 1;
    const int lc   = (tid & 1) * 32;

    // load Q (pre-scaled into base-2 softmax domain)
    const float sc = 0.125f * 1.4426950408889634f;
    {
        const float* qp = Qg + (size_t)(qt * 64 + lrow) * DM + h * HD + lc;
#pragma unroll
        for (int i = 0; i < 8; i++) {
            float4 v = *(const float4*)(qp + i * 4);
            uint4 u = make_uint4(f2tf32(v.x * sc), f2tf32(v.y * sc), f2tf32(v.z * sc), f2tf32(v.w * sc));
            *(uint4*)&Qs[lrow * QS_ST + lc + i * 4] = u;
        }
    }

    float o[8][4] = {};
    float m0 = -1e30f, m1 = -1e30f, l0 = 0.0f, l1 = 0.0f;

    for (int j = 0; j <= qt; j++) {
        // load K, V tiles
        {
            const size_t gb = (size_t)(j * 64 + lrow) * DM + h * HD + lc;
#pragma unroll
            for (int i = 0; i < 8; i++) {
                float4 kv = *(const float4*)(Kg + gb + i * 4);
                uint4 uk = make_uint4(f2tf32(kv.x), f2tf32(kv.y), f2tf32(kv.z), f2tf32(kv.w));
                *(uint4*)&KP[lrow * QS_ST + lc + i * 4] = uk;
                float4 vv = *(const float4*)(Vg + gb + i * 4);
                uint4 uv = make_uint4(f2tf32(vv.x), f2tf32(vv.y), f2tf32(vv.z), f2tf32(vv.w));
                *(uint4*)&Vs[lrow * VS_ST + lc + i * 4] = uv;
            }
        }
        __syncthreads();

        // S = Q K^T  (already includes softmax scale, base-2)
        float sv[8][4] = {};
#pragma unroll
        for (int ks = 0; ks < 8; ks++) {
            const int k0 = ks * 8;
            uint32_t a0 = Qs[(wm + g) * QS_ST + k0 + tg];
            uint32_t a1 = Qs[(wm + g + 8) * QS_ST + k0 + tg];
            uint32_t a2 = Qs[(wm + g) * QS_ST + k0 + tg + 4];
            uint32_t a3 = Qs[(wm + g + 8) * QS_ST + k0 + tg + 4];
#pragma unroll
            for (int nt = 0; nt < 8; nt++) {
                uint32_t b0 = KP[(nt * 8 + g) * QS_ST + k0 + tg];
                uint32_t b1 = KP[(nt * 8 + g) * QS_ST + k0 + tg + 4];
                mma8(sv[nt], a0, a1, a2, a3, b0, b1);
            }
        }

        // causal mask on diagonal tile
        if (j == qt) {
            const int r0 = wm + g, r1 = wm + g + 8;
#pragma unroll
            for (int nt = 0; nt < 8; nt++) {
#pragma unroll
                for (int cc = 0; cc < 2; cc++) {
                    const int col = nt * 8 + tg * 2 + cc;
                    if (col > r0) sv[nt][cc]     = -1e30f;
                    if (col > r1) sv[nt][2 + cc] = -1e30f;
                }
            }
        }

        // online softmax (base-2); rows split across a thread-quad
        float mx0 = -1e30f, mx1 = -1e30f;
#pragma unroll
        for (int nt = 0; nt < 8; nt++) {
            mx0 = fmaxf(mx0, fmaxf(sv[nt][0], sv[nt][1]));
            mx1 = fmaxf(mx1, fmaxf(sv[nt][2], sv[nt][3]));
        }
        mx0 = fmaxf(mx0, __shfl_xor_sync(0xffffffffu, mx0, 1));
        mx0 = fmaxf(mx0, __shfl_xor_sync(0xffffffffu, mx0, 2));
        mx1 = fmaxf(mx1, __shfl_xor_sync(0xffffffffu, mx1, 1));
        mx1 = fmaxf(mx1, __shfl_xor_sync(0xffffffffu, mx1, 2));

        const float mn0 = fmaxf(m0, mx0), mn1 = fmaxf(m1, mx1);
        const float al0 = fexp2(m0 - mn0), al1 = fexp2(m1 - mn1);
        float s0 = 0.0f, s1 = 0.0f;
#pragma unroll
        for (int nt = 0; nt < 8; nt++) {
            sv[nt][0] = fexp2(sv[nt][0] - mn0); s0 += sv[nt][0];
            sv[nt][1] = fexp2(sv[nt][1] - mn0); s0 += sv[nt][1];
            sv[nt][2] = fexp2(sv[nt][2] - mn1); s1 += sv[nt][2];
            sv[nt][3] = fexp2(sv[nt][3] - mn1); s1 += sv[nt][3];
        }
        s0 += __shfl_xor_sync(0xffffffffu, s0, 1);
        s0 += __shfl_xor_sync(0xffffffffu, s0, 2);
        s1 += __shfl_xor_sync(0xffffffffu, s1, 1);
        s1 += __shfl_xor_sync(0xffffffffu, s1, 2);
        l0 = l0 * al0 + s0;  l1 = l1 * al1 + s1;
        m0 = mn0;  m1 = mn1;
#pragma unroll
        for (int nt = 0; nt < 8; nt++) {
            o[nt][0] *= al0; o[nt][1] *= al0;
            o[nt][2] *= al1; o[nt][3] *= al1;
        }

        __syncthreads();   // all warps done reading KP as K

        // write P (tf32) into KP buffer
#pragma unroll
        for (int nt = 0; nt < 8; nt++) {
            const int c = nt * 8 + tg * 2;
            KP[(wm + g) * QS_ST + c]         = f2tf32(sv[nt][0]);
            KP[(wm + g) * QS_ST + c + 1]     = f2tf32(sv[nt][1]);
            KP[(wm + g + 8) * QS_ST + c]     = f2tf32(sv[nt][2]);
            KP[(wm + g + 8) * QS_ST + c + 1] = f2tf32(sv[nt][3]);
        }
        __syncthreads();

        // O += P V
#pragma unroll
        for (int ks = 0; ks < 8; ks++) {
            const int k0 = ks * 8;
            uint32_t a0 = KP[(wm + g) * QS_ST + k0 + tg];
            uint32_t a1 = KP[(wm + g + 8) * QS_ST + k0 + tg];
            uint32_t a2 = KP[(wm + g) * QS_ST + k0 + tg + 4];
            uint32_t a3 = KP[(wm + g + 8) * QS_ST + k0 + tg + 4];
#pragma unroll
            for (int nt = 0; nt < 8; nt++) {
                uint32_t b0 = Vs[(k0 + tg) * VS_ST + nt * 8 + g];
                uint32_t b1 = Vs[(k0 + tg + 4) * VS_ST + nt * 8 + g];
                mma8(o[nt], a0, a1, a2, a3, b0, b1);
            }
        }
        __syncthreads();   // before next tile overwrites KP/Vs
    }

    // normalize + store
    const float i0 = 1.0f / l0, i1 = 1.0f / l1;
    const int r0 = qt * 64 + wm + g, r1 = r0 + 8;
#pragma unroll
    for (int nt = 0; nt < 8; nt++) {
        const int c = h * HD + nt * 8 + tg * 2;
        *(float2*)&O[(size_t)r0 * DM + c] = make_float2(o[nt][0] * i0, o[nt][1] * i0);
        *(float2*)&O[(size_t)r1 * DM + c] = make_float2(o[nt][2] * i1, o[nt][3] * i1);
    }
}

// ================= launch =================
extern "C" void kernel_launch(void* const* d_in, const int* in_sizes, int n_in,
                              void* d_out, int out_size)
{
    (void)in_sizes; (void)n_in; (void)out_size;
    const float* x  = (const float*)d_in[0];
    const float* Wq = (const float*)d_in[1];
    const float* Wk = (const float*)d_in[2];
    const float* Wv = (const float*)d_in[3];
    const float* Wp = (const float*)d_in[4];
    float* out = (float*)d_out;

    float *Q, *K, *V, *att;
    cudaGetSymbolAddress((void**)&Q,   g_Q);
    cudaGetSymbolAddress((void**)&K,   g_K);
    cudaGetSymbolAddress((void**)&V,   g_V);
    cudaGetSymbolAddress((void**)&att, g_att);

    const int flash_smem = FLASH_SMEM_WORDS * (int)sizeof(uint32_t);  // 53248 B
    cudaFuncSetAttribute(flash_tc, cudaFuncAttributeMaxDynamicSharedMemorySize, flash_smem);

    // fused QKV projection
    dim3 gq(DM / 128, SEQ / 128, 3);
    gemm_tc<<<gq, 256>>>(x, Wq, Wk, Wv, Q, K, V, SEQ, DM, DM);

    // causal flash attention
    dim3 gf(SEQ / 64, NH);
    flash_tc<<<gf, 128, flash_smem>>>(Q, K, V, att);

    // output projection
    dim3 gp(DM / 128, SEQ / 128, 1);
    gemm_tc<<<gp, 256>>>(att, Wp, Wp, Wp, out, out, out, SEQ, DM, DM);
}

// round 4
// speedup vs baseline: 2.7285x; 1.4065x over previous
#include <cuda_runtime.h>
#include <cstdint>

#define SEQ 4096
#define DM  768
#define NH  12
#define HD  64

// ---------------- scratch (no allocations allowed) ----------------
__device__ float g_Q[SEQ * DM];
__device__ float g_K[SEQ * DM];
__device__ float g_V[SEQ * DM];
__device__ float g_att[SEQ * DM];

// ---------------- helpers ----------------
__device__ __forceinline__ uint32_t f2tf32(float x) {
    uint32_t y;
    asm("cvt.rna.tf32.f32 %0, %1;" : "=r"(y) : "f"(x));
    return y;
}
__device__ __forceinline__ float fexp2(float x) {
    float y;
    asm("ex2.approx.ftz.f32 %0, %1;" : "=f"(y) : "f"(x));
    return y;
}
// D += A*B  (m16n8k8 tf32, fp32 accumulate)
__device__ __forceinline__ void mma8(float* d,
                                     uint32_t a0, uint32_t a1, uint32_t a2, uint32_t a3,
                                     uint32_t b0, uint32_t b1) {
    asm volatile(
        "mma.sync.aligned.m16n8k8.row.col.f32.tf32.tf32.f32 "
        "{%0,%1,%2,%3}, {%4,%5,%6,%7}, {%8,%9}, {%0,%1,%2,%3};"
        : "+f"(d[0]), "+f"(d[1]), "+f"(d[2]), "+f"(d[3])
        : "r"(a0), "r"(a1), "r"(a2), "r"(a3), "r"(b0), "r"(b1));
}

// ================= GEMM: C[M,N] = A[M,K] * B[N,K]^T  (tf32 mma.sync) =================
#define GS 36   // smem row stride in words; 36 % 32 == 4 -> frag LDS conflict-free

__global__ __launch_bounds__(256, 2)
void gemm_tc(const float* __restrict__ A,
             const float* __restrict__ B0, const float* __restrict__ B1, const float* __restrict__ B2,
             float* __restrict__ C0, float* __restrict__ C1, float* __restrict__ C2,
             int M, int N, int K)
{
    const float* B = (blockIdx.z == 0) ? B0 : ((blockIdx.z == 1) ? B1 : B2);
    float*       C = (blockIdx.z == 0) ? C0 : ((blockIdx.z == 1) ? C1 : C2);

    __shared__ uint32_t As[128 * GS];
    __shared__ uint32_t Bs[128 * GS];

    const int tid  = threadIdx.x;
    const int wid  = tid >> 5;
    const int lane = tid & 31;
    const int g    = lane >> 2;
    const int tg   = lane & 3;
    const int wm   = (wid >> 2) * 64;
    const int wn   = (wid & 3) * 32;
    const int m0   = blockIdx.y * 128;
    const int n0   = blockIdx.x * 128;

    const int lrow = tid >> 1;
    const int lc   = (tid & 1) * 16;
    const float* Ap = A + (size_t)(m0 + lrow) * K + lc;
    const float* Bp = B + (size_t)(n0 + lrow) * K + lc;

    float4 pa[4], pb[4];
#pragma unroll
    for (int i = 0; i < 4; i++) {
        pa[i] = *(const float4*)(Ap + i * 4);
        pb[i] = *(const float4*)(Bp + i * 4);
    }

    float acc[4][4][4] = {};
    const int T = K / 32;

    for (int t = 0; t < T; t++) {
#pragma unroll
        for (int i = 0; i < 4; i++) {
            uint4 ua = make_uint4(f2tf32(pa[i].x), f2tf32(pa[i].y), f2tf32(pa[i].z), f2tf32(pa[i].w));
            *(uint4*)&As[lrow * GS + lc + i * 4] = ua;
            uint4 ub = make_uint4(f2tf32(pb[i].x), f2tf32(pb[i].y), f2tf32(pb[i].z), f2tf32(pb[i].w));
            *(uint4*)&Bs[lrow * GS + lc + i * 4] = ub;
        }
        __syncthreads();

        if (t + 1 < T) {
#pragma unroll
            for (int i = 0; i < 4; i++) {
                pa[i] = *(const float4*)(Ap + (t + 1) * 32 + i * 4);
                pb[i] = *(const float4*)(Bp + (t + 1) * 32 + i * 4);
            }
        }

#pragma unroll
        for (int ks = 0; ks < 4; ks++) {
            const int k0 = ks * 8;
            uint32_t af[4][4];
#pragma unroll
            for (int mt = 0; mt < 4; mt++) {
                const int r = wm + mt * 16 + g;
                af[mt][0] = As[r * GS + k0 + tg];
                af[mt][1] = As[(r + 8) * GS + k0 + tg];
                af[mt][2] = As[r * GS + k0 + tg + 4];
                af[mt][3] = As[(r + 8) * GS + k0 + tg + 4];
            }
#pragma unroll
            for (int nt = 0; nt < 4; nt++) {
                const int rn = wn + nt * 8 + g;
                uint32_t b0 = Bs[rn * GS + k0 + tg];
                uint32_t b1 = Bs[rn * GS + k0 + tg + 4];
#pragma unroll
                for (int mt = 0; mt < 4; mt++)
                    mma8(acc[mt][nt], af[mt][0], af[mt][1], af[mt][2], af[mt][3], b0, b1);
            }
        }
        __syncthreads();
    }

#pragma unroll
    for (int mt = 0; mt < 4; mt++) {
        const int r0 = m0 + wm + mt * 16 + g;
#pragma unroll
        for (int nt = 0; nt < 4; nt++) {
            const int c = n0 + wn + nt * 8 + tg * 2;
            *(float2*)&C[(size_t)r0 * N + c]       = make_float2(acc[mt][nt][0], acc[mt][nt][1]);
            *(float2*)&C[(size_t)(r0 + 8) * N + c] = make_float2(acc[mt][nt][2], acc[mt][nt][3]);
        }
    }
}

// ================= Flash attention v2 =================
// block: 128 q-rows x 1 head, 8 warps (warp owns 16 rows); KV tile 64
// syncs/iter: 2.  K/V tile j+1 prefetched into registers during compute of j.
#define QS_ST 68   // 68 % 32 == 4 : frag pattern 4g+tg conflict-free
#define VS_ST 72   // 72 % 32 == 8 : V b-frag pattern 8tg+g conflict-free
#define SM_Q  0
#define SM_K  (128 * QS_ST)                 // 8704
#define SM_V  (SM_K + 64 * QS_ST)           // 13056
#define SM_P  (SM_V + 64 * VS_ST)           // 17664
#define FLASH_SMEM_WORDS (SM_P + 128 * QS_ST)  // 26368 words = 105472 B

__global__ __launch_bounds__(256, 2)
void flash_tc(const float* __restrict__ Qg, const float* __restrict__ Kg,
              const float* __restrict__ Vg, float* __restrict__ O)
{
    extern __shared__ uint32_t sm[];
    uint32_t* Qs = sm + SM_Q;
    uint32_t* Ks = sm + SM_K;
    uint32_t* Vs = sm + SM_V;
    uint32_t* Ps = sm + SM_P;

    const int qt   = (int)gridDim.x - 1 - blockIdx.x;  // longest blocks first
    const int h    = blockIdx.y;
    const int tid  = threadIdx.x;
    const int lane = tid & 31;
    const int g    = lane >> 2;
    const int tg   = lane & 3;
    const int wm   = (tid >> 5) * 16;   // warp row offset (8 warps x 16 rows)

    // ---- load Q tile (128 rows), pre-scaled into base-2 softmax domain ----
    const float sc = 0.125f * 1.4426950408889634f;
    {
        const int lrow = tid >> 1;
        const int lc   = (tid & 1) * 32;
        const float* qp = Qg + (size_t)(qt * 128 + lrow) * DM + h * HD + lc;
#pragma unroll
        for (int i = 0; i < 8; i++) {
            float4 v = *(const float4*)(qp + i * 4);
            uint4 u = make_uint4(f2tf32(v.x * sc), f2tf32(v.y * sc), f2tf32(v.z * sc), f2tf32(v.w * sc));
            *(uint4*)&Qs[lrow * QS_ST + lc + i * 4] = u;
        }
    }

    // ---- K/V loader mapping: 4 threads per row, 16 floats each ----
    const int krow = tid >> 2;          // 0..63
    const int kc   = (tid & 3) * 16;    // 0,16,32,48

    float4 pk[4], pv[4];
    {
        const size_t gb = (size_t)krow * DM + h * HD + kc;   // tile 0
#pragma unroll
        for (int i = 0; i < 4; i++) {
            pk[i] = *(const float4*)(Kg + gb + i * 4);
            pv[i] = *(const float4*)(Vg + gb + i * 4);
        }
    }

    float o[8][4] = {};
    float m0 = -1e30f, m1 = -1e30f, l0 = 0.0f, l1 = 0.0f;
    const int jmax = 2 * qt + 1;

    for (int j = 0; j <= jmax; j++) {
        // ---- commit prefetched K/V tile to smem (tf32-rounded) ----
#pragma unroll
        for (int i = 0; i < 4; i++) {
            uint4 uk = make_uint4(f2tf32(pk[i].x), f2tf32(pk[i].y), f2tf32(pk[i].z), f2tf32(pk[i].w));
            *(uint4*)&Ks[krow * QS_ST + kc + i * 4] = uk;
            uint4 uv = make_uint4(f2tf32(pv[i].x), f2tf32(pv[i].y), f2tf32(pv[i].z), f2tf32(pv[i].w));
            *(uint4*)&Vs[krow * VS_ST + kc + i * 4] = uv;
        }
        __syncthreads();

        // ---- prefetch next K/V tile into registers (overlaps all compute below) ----
        if (j < jmax) {
            const size_t gb = (size_t)((j + 1) * 64 + krow) * DM + h * HD + kc;
#pragma unroll
            for (int i = 0; i < 4; i++) {
                pk[i] = *(const float4*)(Kg + gb + i * 4);
                pv[i] = *(const float4*)(Vg + gb + i * 4);
            }
        }

        // ---- S = Q K^T (scale folded into Q) ----
        float sv[8][4] = {};
#pragma unroll
        for (int ks = 0; ks < 8; ks++) {
            const int k0 = ks * 8;
            uint32_t a0 = Qs[(wm + g) * QS_ST + k0 + tg];
            uint32_t a1 = Qs[(wm + g + 8) * QS_ST + k0 + tg];
            uint32_t a2 = Qs[(wm + g) * QS_ST + k0 + tg + 4];
            uint32_t a3 = Qs[(wm + g + 8) * QS_ST + k0 + tg + 4];
#pragma unroll
            for (int nt = 0; nt < 8; nt++) {
                uint32_t b0 = Ks[(nt * 8 + g) * QS_ST + k0 + tg];
                uint32_t b1 = Ks[(nt * 8 + g) * QS_ST + k0 + tg + 4];
                mma8(sv[nt], a0, a1, a2, a3, b0, b1);
            }
        }

        // ---- causal mask (global indices; only the last two tiles intersect) ----
        if (j >= 2 * qt) {
            const int r0 = qt * 128 + wm + g, r1 = r0 + 8;
            const int cb = j * 64;
#pragma unroll
            for (int nt = 0; nt < 8; nt++) {
#pragma unroll
                for (int cc = 0; cc < 2; cc++) {
                    const int col = cb + nt * 8 + tg * 2 + cc;
                    if (col > r0) sv[nt][cc]     = -1e30f;
                    if (col > r1) sv[nt][2 + cc] = -1e30f;
                }
            }
        }

        // ---- online softmax (base-2); rows split across thread-quad ----
        float mx0 = -1e30f, mx1 = -1e30f;
#pragma unroll
        for (int nt = 0; nt < 8; nt++) {
            mx0 = fmaxf(mx0, fmaxf(sv[nt][0], sv[nt][1]));
            mx1 = fmaxf(mx1, fmaxf(sv[nt][2], sv[nt][3]));
        }
        mx0 = fmaxf(mx0, __shfl_xor_sync(0xffffffffu, mx0, 1));
        mx0 = fmaxf(mx0, __shfl_xor_sync(0xffffffffu, mx0, 2));
        mx1 = fmaxf(mx1, __shfl_xor_sync(0xffffffffu, mx1, 1));
        mx1 = fmaxf(mx1, __shfl_xor_sync(0xffffffffu, mx1, 2));

        const float mn0 = fmaxf(m0, mx0), mn1 = fmaxf(m1, mx1);
        const float al0 = fexp2(m0 - mn0), al1 = fexp2(m1 - mn1);
        float s0 = 0.0f, s1 = 0.0f;
#pragma unroll
        for (int nt = 0; nt < 8; nt++) {
            sv[nt][0] = fexp2(sv[nt][0] - mn0); s0 += sv[nt][0];
            sv[nt][1] = fexp2(sv[nt][1] - mn0); s0 += sv[nt][1];
            sv[nt][2] = fexp2(sv[nt][2] - mn1); s1 += sv[nt][2];
            sv[nt][3] = fexp2(sv[nt][3] - mn1); s1 += sv[nt][3];
        }
        s0 += __shfl_xor_sync(0xffffffffu, s0, 1);
        s0 += __shfl_xor_sync(0xffffffffu, s0, 2);
        s1 += __shfl_xor_sync(0xffffffffu, s1, 1);
        s1 += __shfl_xor_sync(0xffffffffu, s1, 2);
        l0 = l0 * al0 + s0;  l1 = l1 * al1 + s1;
        m0 = mn0;  m1 = mn1;
#pragma unroll
        for (int nt = 0; nt < 8; nt++) {
            o[nt][0] *= al0; o[nt][1] *= al0;
            o[nt][2] *= al1; o[nt][3] *= al1;
        }

        // ---- P to smem (warp-local rows: no block sync needed) ----
#pragma unroll
        for (int nt = 0; nt < 8; nt++) {
            const int c = nt * 8 + tg * 2;
            Ps[(wm + g) * QS_ST + c]         = f2tf32(sv[nt][0]);
            Ps[(wm + g) * QS_ST + c + 1]     = f2tf32(sv[nt][1]);
            Ps[(wm + g + 8) * QS_ST + c]     = f2tf32(sv[nt][2]);
            Ps[(wm + g + 8) * QS_ST + c + 1] = f2tf32(sv[nt][3]);
        }
        __syncwarp();

        // ---- O += P V ----
#pragma unroll
        for (int ks = 0; ks < 8; ks++) {
            const int k0 = ks * 8;
            uint32_t a0 = Ps[(wm + g) * QS_ST + k0 + tg];
            uint32_t a1 = Ps[(wm + g + 8) * QS_ST + k0 + tg];
            uint32_t a2 = Ps[(wm + g) * QS_ST + k0 + tg + 4];
            uint32_t a3 = Ps[(wm + g + 8) * QS_ST + k0 + tg + 4];
#pragma unroll
            for (int nt = 0; nt < 8; nt++) {
                uint32_t b0 = Vs[(k0 + tg) * VS_ST + nt * 8 + g];
                uint32_t b1 = Vs[(k0 + tg + 4) * VS_ST + nt * 8 + g];
                mma8(o[nt], a0, a1, a2, a3, b0, b1);
            }
        }
        __syncthreads();   // Ks/Vs fully consumed before next tile's stores
    }

    // ---- normalize + store ----
    const float i0 = 1.0f / l0, i1 = 1.0f / l1;
    const int r0 = qt * 128 + wm + g, r1 = r0 + 8;
#pragma unroll
    for (int nt = 0; nt < 8; nt++) {
        const int c = h * HD + nt * 8 + tg * 2;
        *(float2*)&O[(size_t)r0 * DM + c] = make_float2(o[nt][0] * i0, o[nt][1] * i0);
        *(float2*)&O[(size_t)r1 * DM + c] = make_float2(o[nt][2] * i1, o[nt][3] * i1);
    }
}

// ================= launch =================
extern "C" void kernel_launch(void* const* d_in, const int* in_sizes, int n_in,
                              void* d_out, int out_size)
{
    (void)in_sizes; (void)n_in; (void)out_size;
    const float* x  = (const float*)d_in[0];
    const float* Wq = (const float*)d_in[1];
    const float* Wk = (const float*)d_in[2];
    const float* Wv = (const float*)d_in[3];
    const float* Wp = (const float*)d_in[4];
    float* out = (float*)d_out;

    float *Q, *K, *V, *att;
    cudaGetSymbolAddress((void**)&Q,   g_Q);
    cudaGetSymbolAddress((void**)&K,   g_K);
    cudaGetSymbolAddress((void**)&V,   g_V);
    cudaGetSymbolAddress((void**)&att, g_att);

    const int flash_smem = FLASH_SMEM_WORDS * (int)sizeof(uint32_t);  // 105472 B
    cudaFuncSetAttribute(flash_tc, cudaFuncAttributeMaxDynamicSharedMemorySize, flash_smem);

    // fused QKV projection
    dim3 gq(DM / 128, SEQ / 128, 3);
    gemm_tc<<<gq, 256>>>(x, Wq, Wk, Wv, Q, K, V, SEQ, DM, DM);

    // causal flash attention (128-row q tiles)
    dim3 gf(SEQ / 128, NH);
    flash_tc<<<gf, 256, flash_smem>>>(Q, K, V, att);

    // output projection
    dim3 gp(DM / 128, SEQ / 128, 1);
    gemm_tc<<<gp, 256>>>(att, Wp, Wp, Wp, out, out, out, SEQ, DM, DM);
}

// round 5
// speedup vs baseline: 2.8237x; 1.0349x over previous
#include <cuda_runtime.h>
#include <cstdint>

#define SEQ 4096
#define DM  768
#define NH  12
#define HD  64

// ---------------- scratch (no allocations allowed) ----------------
__device__ float g_Q[SEQ * DM];
__device__ float g_K[SEQ * DM];
__device__ float g_V[SEQ * DM];
__device__ float g_att[SEQ * DM];

// ---------------- helpers ----------------
__device__ __forceinline__ uint32_t f2tf32(float x) {
    uint32_t y;
    asm("cvt.rna.tf32.f32 %0, %1;" : "=r"(y) : "f"(x));
    return y;
}
__device__ __forceinline__ float fexp2(float x) {
    float y;
    asm("ex2.approx.ftz.f32 %0, %1;" : "=f"(y) : "f"(x));
    return y;
}
// D += A*B  (m16n8k8 tf32, fp32 accumulate)
__device__ __forceinline__ void mma8(float* d,
                                     uint32_t a0, uint32_t a1, uint32_t a2, uint32_t a3,
                                     uint32_t b0, uint32_t b1) {
    asm volatile(
        "mma.sync.aligned.m16n8k8.row.col.f32.tf32.tf32.f32 "
        "{%0,%1,%2,%3}, {%4,%5,%6,%7}, {%8,%9}, {%0,%1,%2,%3};"
        : "+f"(d[0]), "+f"(d[1]), "+f"(d[2]), "+f"(d[3])
        : "r"(a0), "r"(a1), "r"(a2), "r"(a3), "r"(b0), "r"(b1));
}

// ================= GEMM: C[M,N] = A[M,K] * B[N,K]^T  (tf32 mma.sync) =================
#define GS 36   // smem row stride in words; 36 % 32 == 4 -> frag LDS conflict-free

__global__ __launch_bounds__(256, 2)
void gemm_tc(const float* __restrict__ A,
             const float* __restrict__ B0, const float* __restrict__ B1, const float* __restrict__ B2,
             float* __restrict__ C0, float* __restrict__ C1, float* __restrict__ C2,
             int M, int N, int K)
{
    const float* B = (blockIdx.z == 0) ? B0 : ((blockIdx.z == 1) ? B1 : B2);
    float*       C = (blockIdx.z == 0) ? C0 : ((blockIdx.z == 1) ? C1 : C2);

    __shared__ uint32_t As[128 * GS];
    __shared__ uint32_t Bs[128 * GS];

    const int tid  = threadIdx.x;
    const int wid  = tid >> 5;
    const int lane = tid & 31;
    const int g    = lane >> 2;
    const int tg   = lane & 3;
    const int wm   = (wid >> 2) * 64;
    const int wn   = (wid & 3) * 32;
    const int m0   = blockIdx.y * 128;
    const int n0   = blockIdx.x * 128;

    const int lrow = tid >> 1;
    const int lc   = (tid & 1) * 16;
    const float* Ap = A + (size_t)(m0 + lrow) * K + lc;
    const float* Bp = B + (size_t)(n0 + lrow) * K + lc;

    float4 pa[4], pb[4];
#pragma unroll
    for (int i = 0; i < 4; i++) {
        pa[i] = *(const float4*)(Ap + i * 4);
        pb[i] = *(const float4*)(Bp + i * 4);
    }

    float acc[4][4][4] = {};
    const int T = K / 32;

    for (int t = 0; t < T; t++) {
#pragma unroll
        for (int i = 0; i < 4; i++) {
            uint4 ua = make_uint4(f2tf32(pa[i].x), f2tf32(pa[i].y), f2tf32(pa[i].z), f2tf32(pa[i].w));
            *(uint4*)&As[lrow * GS + lc + i * 4] = ua;
            uint4 ub = make_uint4(f2tf32(pb[i].x), f2tf32(pb[i].y), f2tf32(pb[i].z), f2tf32(pb[i].w));
            *(uint4*)&Bs[lrow * GS + lc + i * 4] = ub;
        }
        __syncthreads();

        if (t + 1 < T) {
#pragma unroll
            for (int i = 0; i < 4; i++) {
                pa[i] = *(const float4*)(Ap + (t + 1) * 32 + i * 4);
                pb[i] = *(const float4*)(Bp + (t + 1) * 32 + i * 4);
            }
        }

#pragma unroll
        for (int ks = 0; ks < 4; ks++) {
            const int k0 = ks * 8;
            uint32_t af[4][4];
#pragma unroll
            for (int mt = 0; mt < 4; mt++) {
                const int r = wm + mt * 16 + g;
                af[mt][0] = As[r * GS + k0 + tg];
                af[mt][1] = As[(r + 8) * GS + k0 + tg];
                af[mt][2] = As[r * GS + k0 + tg + 4];
                af[mt][3] = As[(r + 8) * GS + k0 + tg + 4];
            }
#pragma unroll
            for (int nt = 0; nt < 4; nt++) {
                const int rn = wn + nt * 8 + g;
                uint32_t b0 = Bs[rn * GS + k0 + tg];
                uint32_t b1 = Bs[rn * GS + k0 + tg + 4];
#pragma unroll
                for (int mt = 0; mt < 4; mt++)
                    mma8(acc[mt][nt], af[mt][0], af[mt][1], af[mt][2], af[mt][3], b0, b1);
            }
        }
        __syncthreads();
    }

#pragma unroll
    for (int mt = 0; mt < 4; mt++) {
        const int r0 = m0 + wm + mt * 16 + g;
#pragma unroll
        for (int nt = 0; nt < 4; nt++) {
            const int c = n0 + wn + nt * 8 + tg * 2;
            *(float2*)&C[(size_t)r0 * N + c]       = make_float2(acc[mt][nt][0], acc[mt][nt][1]);
            *(float2*)&C[(size_t)(r0 + 8) * N + c] = make_float2(acc[mt][nt][2], acc[mt][nt][3]);
        }
    }
}

// ================= Flash attention v3 =================
// 128-row q-tile, 4 warps (warp owns 32 rows), 128 threads, 2 CTAs/SM.
// Staggered prefetch: V(j) hidden behind S+softmax, K(j+1) hidden behind PV.
#define QS_ST 68   // 68 % 32 == 4 : A/B frag pattern 4g+tg conflict-free
#define VS_ST 72   // 72 % 32 == 8 : V b-frag pattern 8tg+g conflict-free
#define SM_Q  0
#define SM_K  (128 * QS_ST)                 // 8704
#define SM_V  (SM_K + 64 * QS_ST)           // 13056
#define SM_P  (SM_V + 64 * VS_ST)           // 17664
#define FLASH_SMEM_WORDS (SM_P + 128 * QS_ST)  // 26368 words = 105472 B

__global__ __launch_bounds__(128, 2)
void flash_tc(const float* __restrict__ Qg, const float* __restrict__ Kg,
              const float* __restrict__ Vg, float* __restrict__ O)
{
    extern __shared__ uint32_t sm[];
    uint32_t* Qs = sm + SM_Q;
    uint32_t* Ks = sm + SM_K;
    uint32_t* Vs = sm + SM_V;
    uint32_t* Ps = sm + SM_P;

    const int qt   = (int)gridDim.x - 1 - blockIdx.x;  // longest blocks first
    const int h    = blockIdx.y;
    const int tid  = threadIdx.x;
    const int lane = tid & 31;
    const int g    = lane >> 2;
    const int tg   = lane & 3;
    const int wm   = (tid >> 5) * 32;   // 4 warps x 32 rows

    // ---- load Q tile (1 row per thread), pre-scaled into base-2 domain ----
    const float sc = 0.125f * 1.4426950408889634f;
    {
        const float* qp = Qg + (size_t)(qt * 128 + tid) * DM + h * HD;
#pragma unroll
        for (int i = 0; i < 16; i++) {
            float4 v = *(const float4*)(qp + i * 4);
            uint4 u = make_uint4(f2tf32(v.x * sc), f2tf32(v.y * sc), f2tf32(v.z * sc), f2tf32(v.w * sc));
            *(uint4*)&Qs[tid * QS_ST + i * 4] = u;
        }
    }

    // ---- K/V loader mapping: 2 threads per row, 32 floats each ----
    const int krow = tid >> 1;          // 0..63
    const int kc   = (tid & 1) * 32;    // 0 or 32

    float4 pk[8];
    {
        const size_t gb = (size_t)krow * DM + h * HD + kc;   // K tile 0
#pragma unroll
        for (int i = 0; i < 8; i++) pk[i] = *(const float4*)(Kg + gb + i * 4);
    }

    float o[2][8][4] = {};
    float m_[4], l_[4];
#pragma unroll
    for (int i = 0; i < 4; i++) { m_[i] = -1e30f; l_[i] = 0.0f; }

    const int jmax = 2 * qt + 1;

    for (int j = 0; j <= jmax; j++) {
        // ---- commit prefetched K tile ----
#pragma unroll
        for (int i = 0; i < 8; i++) {
            uint4 uk = make_uint4(f2tf32(pk[i].x), f2tf32(pk[i].y), f2tf32(pk[i].z), f2tf32(pk[i].w));
            *(uint4*)&Ks[krow * QS_ST + kc + i * 4] = uk;
        }
        __syncthreads();   // sync A: Ks ready (also: prior PV done -> Vs writable)

        // ---- prefetch V tile j (consumed after softmax; hidden behind S+softmax) ----
        float4 pv[8];
        {
            const size_t gb = (size_t)(j * 64 + krow) * DM + h * HD + kc;
#pragma unroll
            for (int i = 0; i < 8; i++) pv[i] = *(const float4*)(Vg + gb + i * 4);
        }

        // ---- S = Q K^T (2 m-blocks x 8 n-tiles) ----
        float sv[2][8][4] = {};
#pragma unroll
        for (int ks = 0; ks < 8; ks++) {
            const int k0 = ks * 8;
            uint32_t a[2][4];
#pragma unroll
            for (int mb = 0; mb < 2; mb++) {
                const int r = wm + mb * 16 + g;
                a[mb][0] = Qs[r * QS_ST + k0 + tg];
                a[mb][1] = Qs[(r + 8) * QS_ST + k0 + tg];
                a[mb][2] = Qs[r * QS_ST + k0 + tg + 4];
                a[mb][3] = Qs[(r + 8) * QS_ST + k0 + tg + 4];
            }
#pragma unroll
            for (int nt = 0; nt < 8; nt++) {
                uint32_t b0 = Ks[(nt * 8 + g) * QS_ST + k0 + tg];
                uint32_t b1 = Ks[(nt * 8 + g) * QS_ST + k0 + tg + 4];
                mma8(sv[0][nt], a[0][0], a[0][1], a[0][2], a[0][3], b0, b1);
                mma8(sv[1][nt], a[1][0], a[1][1], a[1][2], a[1][3], b0, b1);
            }
        }

        // ---- causal mask (only last two KV tiles intersect the diagonal) ----
        if (j >= 2 * qt) {
            const int cb = j * 64;
#pragma unroll
            for (int mb = 0; mb < 2; mb++) {
                const int r0 = qt * 128 + wm + mb * 16 + g, r1 = r0 + 8;
#pragma unroll
                for (int nt = 0; nt < 8; nt++) {
#pragma unroll
                    for (int cc = 0; cc < 2; cc++) {
                        const int col = cb + nt * 8 + tg * 2 + cc;
                        if (col > r0) sv[mb][nt][cc]     = -1e30f;
                        if (col > r1) sv[mb][nt][2 + cc] = -1e30f;
                    }
                }
            }
        }

        // ---- online softmax (base-2); 4 row-groups, quad shfl reductions ----
#pragma unroll
        for (int mb = 0; mb < 2; mb++) {
            float mx0 = -1e30f, mx1 = -1e30f;
#pragma unroll
            for (int nt = 0; nt < 8; nt++) {
                mx0 = fmaxf(mx0, fmaxf(sv[mb][nt][0], sv[mb][nt][1]));
                mx1 = fmaxf(mx1, fmaxf(sv[mb][nt][2], sv[mb][nt][3]));
            }
            mx0 = fmaxf(mx0, __shfl_xor_sync(0xffffffffu, mx0, 1));
            mx0 = fmaxf(mx0, __shfl_xor_sync(0xffffffffu, mx0, 2));
            mx1 = fmaxf(mx1, __shfl_xor_sync(0xffffffffu, mx1, 1));
            mx1 = fmaxf(mx1, __shfl_xor_sync(0xffffffffu, mx1, 2));

            const int g0 = 2 * mb, g1 = 2 * mb + 1;
            const float mn0 = fmaxf(m_[g0], mx0), mn1 = fmaxf(m_[g1], mx1);
            const float al0 = fexp2(m_[g0] - mn0), al1 = fexp2(m_[g1] - mn1);
            float s0 = 0.0f, s1 = 0.0f;
#pragma unroll
            for (int nt = 0; nt < 8; nt++) {
                sv[mb][nt][0] = fexp2(sv[mb][nt][0] - mn0); s0 += sv[mb][nt][0];
                sv[mb][nt][1] = fexp2(sv[mb][nt][1] - mn0); s0 += sv[mb][nt][1];
                sv[mb][nt][2] = fexp2(sv[mb][nt][2] - mn1); s1 += sv[mb][nt][2];
                sv[mb][nt][3] = fexp2(sv[mb][nt][3] - mn1); s1 += sv[mb][nt][3];
            }
            s0 += __shfl_xor_sync(0xffffffffu, s0, 1);
            s0 += __shfl_xor_sync(0xffffffffu, s0, 2);
            s1 += __shfl_xor_sync(0xffffffffu, s1, 1);
            s1 += __shfl_xor_sync(0xffffffffu, s1, 2);
            l_[g0] = l_[g0] * al0 + s0;  l_[g1] = l_[g1] * al1 + s1;
            m_[g0] = mn0;  m_[g1] = mn1;
#pragma unroll
            for (int nt = 0; nt < 8; nt++) {
                o[mb][nt][0] *= al0; o[mb][nt][1] *= al0;
                o[mb][nt][2] *= al1; o[mb][nt][3] *= al1;
            }
        }

        // ---- commit V tile (Vs writable since sync A) ----
#pragma unroll
        for (int i = 0; i < 8; i++) {
            uint4 uv = make_uint4(f2tf32(pv[i].x), f2tf32(pv[i].y), f2tf32(pv[i].z), f2tf32(pv[i].w));
            *(uint4*)&Vs[krow * VS_ST + kc + i * 4] = uv;
        }

        // ---- P to smem (warp-local rows) ----
#pragma unroll
        for (int mb = 0; mb < 2; mb++) {
            const int r = wm + mb * 16 + g;
#pragma unroll
            for (int nt = 0; nt < 8; nt++) {
                const int c = nt * 8 + tg * 2;
                Ps[r * QS_ST + c]           = f2tf32(sv[mb][nt][0]);
                Ps[r * QS_ST + c + 1]       = f2tf32(sv[mb][nt][1]);
                Ps[(r + 8) * QS_ST + c]     = f2tf32(sv[mb][nt][2]);
                Ps[(r + 8) * QS_ST + c + 1] = f2tf32(sv[mb][nt][3]);
            }
        }

        // ---- prefetch K tile j+1 (hidden behind PV) ----
        if (j < jmax) {
            const size_t gb = (size_t)((j + 1) * 64 + krow) * DM + h * HD + kc;
#pragma unroll
            for (int i = 0; i < 8; i++) pk[i] = *(const float4*)(Kg + gb + i * 4);
        }
        __syncthreads();   // sync B: Vs ready (and own P visible to own warp)

        // ---- O += P V ----
#pragma unroll
        for (int ks = 0; ks < 8; ks++) {
            const int k0 = ks * 8;
            uint32_t a[2][4];
#pragma unroll
            for (int mb = 0; mb < 2; mb++) {
                const int r = wm + mb * 16 + g;
                a[mb][0] = Ps[r * QS_ST + k0 + tg];
                a[mb][1] = Ps[(r + 8) * QS_ST + k0 + tg];
                a[mb][2] = Ps[r * QS_ST + k0 + tg + 4];
                a[mb][3] = Ps[(r + 8) * QS_ST + k0 + tg + 4];
            }
#pragma unroll
            for (int nt = 0; nt < 8; nt++) {
                uint32_t b0 = Vs[(k0 + tg) * VS_ST + nt * 8 + g];
                uint32_t b1 = Vs[(k0 + tg + 4) * VS_ST + nt * 8 + g];
                mma8(o[0][nt], a[0][0], a[0][1], a[0][2], a[0][3], b0, b1);
                mma8(o[1][nt], a[1][0], a[1][1], a[1][2], a[1][3], b0, b1);
            }
        }
        // no trailing sync needed: Ks rewrite races nothing (readers done before sync B);
        // Vs rewrite of iter j+1 happens after its sync A, which orders all PV reads of iter j.
    }

    // ---- normalize + store ----
#pragma unroll
    for (int mb = 0; mb < 2; mb++) {
        const float i0 = 1.0f / l_[2 * mb], i1 = 1.0f / l_[2 * mb + 1];
        const int r0 = qt * 128 + wm + mb * 16 + g, r1 = r0 + 8;
#pragma unroll
        for (int nt = 0; nt < 8; nt++) {
            const int c = h * HD + nt * 8 + tg * 2;
            *(float2*)&O[(size_t)r0 * DM + c] = make_float2(o[mb][nt][0] * i0, o[mb][nt][1] * i0);
            *(float2*)&O[(size_t)r1 * DM + c] = make_float2(o[mb][nt][2] * i1, o[mb][nt][3] * i1);
        }
    }
}

// ================= launch =================
extern "C" void kernel_launch(void* const* d_in, const int* in_sizes, int n_in,
                              void* d_out, int out_size)
{
    (void)in_sizes; (void)n_in; (void)out_size;
    const float* x  = (const float*)d_in[0];
    const float* Wq = (const float*)d_in[1];
    const float* Wk = (const float*)d_in[2];
    const float* Wv = (const float*)d_in[3];
    const float* Wp = (const float*)d_in[4];
    float* out = (float*)d_out;

    float *Q, *K, *V, *att;
    cudaGetSymbolAddress((void**)&Q,   g_Q);
    cudaGetSymbolAddress((void**)&K,   g_K);
    cudaGetSymbolAddress((void**)&V,   g_V);
    cudaGetSymbolAddress((void**)&att, g_att);

    const int flash_smem = FLASH_SMEM_WORDS * (int)sizeof(uint32_t);  // 105472 B
    cudaFuncSetAttribute(flash_tc, cudaFuncAttributeMaxDynamicSharedMemorySize, flash_smem);

    // fused QKV projection
    dim3 gq(DM / 128, SEQ / 128, 3);
    gemm_tc<<<gq, 256>>>(x, Wq, Wk, Wv, Q, K, V, SEQ, DM, DM);

    // causal flash attention (128-row q tiles, 4 warps of 32 rows)
    dim3 gf(SEQ / 128, NH);
    flash_tc<<<gf, 128, flash_smem>>>(Q, K, V, att);

    // output projection
    dim3 gp(DM / 128, SEQ / 128, 1);
    gemm_tc<<<gp, 256>>>(att, Wp, Wp, Wp, out, out, out, SEQ, DM, DM);
}